// round 13
// baseline (speedup 1.0000x reference)
#include <cuda_runtime.h>
#include <cuda_fp16.h>
#include <cstdint>
#include <cstddef>

#define B_TOT 4096
#define NTOK  49
#define DIM   128
#define NH    4
#define HD    32
#define NW    64
#define SCALE 0.17677669529663687f   // 32^-0.5

#define GRID_PERSIST 444              // 3 CTAs x 148 SMs

// ---------------- device scratch ----------------
// fp16 weight B-fragments: per (kt, jt, lane) -> uint2 {b0, b1} (each = fp16x2)
// q rows (n < 128) pre-scaled by SCALE.
__device__ uint2 g_wqkv16[8 * 48 * 32];
__device__ uint2 g_wproj16[8 * 16 * 32];
__device__ float g_qkvb[384];          // qkv bias, q part pre-scaled
// bias+mask, padded: [NW][NH][64 rows][56 cols]; cols>=49 = -1e30, rows>=49 = 0
#define BM_R 64
#define BM_C 56
__device__ float g_bm[NW * NH * BM_R * BM_C];

// ---------------- helpers ----------------
__device__ __forceinline__ uint32_t pack_h2(float a, float b) {
    __half2 h = __floats2half2_rn(a, b);
    return *reinterpret_cast<uint32_t*>(&h);
}

__device__ __forceinline__ void mma_f16(float c[4],
                                        uint32_t a0, uint32_t a1, uint32_t a2, uint32_t a3,
                                        uint32_t b0, uint32_t b1) {
    asm volatile(
        "mma.sync.aligned.m16n8k16.row.col.f32.f16.f16.f32 "
        "{%0,%1,%2,%3}, {%4,%5,%6,%7}, {%8,%9}, {%0,%1,%2,%3};\n"
        : "+f"(c[0]), "+f"(c[1]), "+f"(c[2]), "+f"(c[3])
        : "r"(a0), "r"(a1), "r"(a2), "r"(a3), "r"(b0), "r"(b1));
}

// ---------------- merged prep kernel (one launch) ----------------
__global__ void pack_all_kernel(const float* __restrict__ qkv_w,
                                const float* __restrict__ proj_w,
                                const float* __restrict__ qkv_b,
                                const float* __restrict__ mask,
                                const float* __restrict__ rpb,
                                const int*   __restrict__ rel_index) {
    int idx = blockIdx.x * blockDim.x + threadIdx.x;

    if (idx < 8 * 48 * 32) {
        int kt   = idx / (48 * 32);
        int jt   = (idx / 32) % 48;
        int lane = idx % 32;
        int n    = jt * 8 + (lane >> 2);
        int k0   = kt * 16 + (lane & 3) * 2;
        float s  = (n < 128) ? SCALE : 1.f;   // fold softmax scale into q weights
        uint2 v;
        v.x = pack_h2(qkv_w[n * DIM + k0] * s,     qkv_w[n * DIM + k0 + 1] * s);
        v.y = pack_h2(qkv_w[n * DIM + k0 + 8] * s, qkv_w[n * DIM + k0 + 9] * s);
        g_wqkv16[idx] = v;
    }
    if (idx < 8 * 16 * 32) {
        int kt   = idx / (16 * 32);
        int jt   = (idx / 32) % 16;
        int lane = idx % 32;
        int n    = jt * 8 + (lane >> 2);
        int k0   = kt * 16 + (lane & 3) * 2;
        uint2 v;
        v.x = pack_h2(proj_w[n * DIM + k0],     proj_w[n * DIM + k0 + 1]);
        v.y = pack_h2(proj_w[n * DIM + k0 + 8], proj_w[n * DIM + k0 + 9]);
        g_wproj16[idx] = v;
    }
    if (idx < 384) {
        g_qkvb[idx] = qkv_b[idx] * ((idx < 128) ? SCALE : 1.f);
    }

    const int total_bm = NW * NH * BM_R * BM_C;
    if (idx < total_bm) {
        int col = idx % BM_C;
        int row = (idx / BM_C) % BM_R;
        int h   = (idx / (BM_C * BM_R)) % NH;
        int w   = idx / (BM_C * BM_R * NH);
        float v;
        if (row < NTOK && col < NTOK) {
            int r = row * NTOK + col;
            v = rpb[rel_index[r] * NH + h] + mask[w * NTOK * NTOK + r];
        } else if (row < NTOK) {
            v = -1e30f;        // pad column: exp -> 0
        } else {
            v = 0.f;           // pad row: discarded later
        }
        g_bm[idx] = v;
    }
}

// ---------------- smem layout (uint32 units) ----------------
// XF @0      : 4096  x / attnout, A-frag-linear fp16  [64x128]
// QF @4096   : 4096  q per head, A-frag-linear fp16   [64x32] x4
// KF @8192   : 4096  k per head, B-frag-linear fp16   [n=64 tok][k=32 dim] x4
// VF @12288  : 4096  v per head, B-frag-linear fp16   [k=64 tok][n=32 dim] x4
#define XF 0
#define QF 4096
#define KF 8192
#define VF 12288
#define SMEM_U32 16384    // 65536 bytes; x3 CTAs = 192 KB/SM

extern __shared__ uint32_t smem_u32[];

// compute 2 jtiles of GEMM1 for this warp (acc[m][j][r])
__device__ __forceinline__ void gemm1_tiles(const uint32_t* sm, int lane, int jt0,
                                            float acc[4][2][4]) {
    #pragma unroll
    for (int m = 0; m < 4; m++)
        #pragma unroll
        for (int j = 0; j < 2; j++)
            #pragma unroll
            for (int r = 0; r < 4; r++) acc[m][j][r] = 0.f;

    #pragma unroll
    for (int kt = 0; kt < 8; ++kt) {
        uint4 af[4];
        #pragma unroll
        for (int m = 0; m < 4; m++)
            af[m] = *(const uint4*)(sm + XF + ((kt * 4 + m) * 32 + lane) * 4);
        #pragma unroll
        for (int j = 0; j < 2; j++) {
            uint2 bw = __ldg(&g_wqkv16[(kt * 48 + jt0 + j) * 32 + lane]);
            #pragma unroll
            for (int m = 0; m < 4; m++)
                mma_f16(acc[m][j], af[m].x, af[m].y, af[m].z, af[m].w, bw.x, bw.y);
        }
    }
}

__global__ void __launch_bounds__(256, 3)
win_attn_kernel(const float* __restrict__ x,
                const float* __restrict__ proj_b,
                float* __restrict__ out) {
    const int tid  = threadIdx.x;
    const int warp = tid >> 5;       // 0..7
    const int lane = tid & 31;
    const int g    = lane >> 2;
    const int tg   = lane & 3;

    uint32_t* sm  = smem_u32;
    char*     smb = reinterpret_cast<char*>(smem_u32);

    #pragma unroll 1
    for (int b = blockIdx.x; b < B_TOT; b += GRID_PERSIST) {

    __syncthreads();   // previous iteration's GEMM3 reads of XF must complete

    // load x into A-frag-linear fp16; pad rows (>=49) written as zero directly
    const float* xb = x + (size_t)b * (NTOK * DIM);
    #pragma unroll
    for (int i = tid; i < 64 * 64; i += 256) {
        int r  = i >> 6;
        int c2 = i & 63;
        int c  = c2 * 2;
        uint32_t val = 0u;
        if (r < NTOK) {
            float2 v = *(const float2*)(xb + r * DIM + c);
            val = pack_h2(v.x, v.y);
        }
        int kt   = c >> 4;
        int m    = r >> 4;
        int ln   = (r & 7) * 4 + (c2 & 3);
        int reg  = ((r >> 3) & 1) | (((c >> 3) & 1) << 1);
        sm[XF + ((kt * 4 + m) * 32 + ln) * 4 + reg] = val;
    }
    __syncthreads();

    // ---------- GEMM1: 3 passes x 2 jtiles/warp; pass 0=q, 1=k, 2=v ----------
    // pass 0: q (weights+bias pre-scaled by SCALE)
    {
        const int jt0 = warp * 2;            // 0..15
        float acc[4][2][4];
        gemm1_tiles(sm, lane, jt0, acc);
        #pragma unroll
        for (int j = 0; j < 2; j++) {
            int jbase = (jt0 + j) * 8;       // 0..127
            int h     = jbase >> 5;
            int cl    = (jbase & 31) + tg * 2;
            float2 bb = *(const float2*)(g_qkvb + jbase + tg * 2);
            int ktq   = cl >> 4;
            int regc  = (cl >> 3) & 1;
            #pragma unroll
            for (int m = 0; m < 4; m++) {
                uint32_t base = QF + h * 1024 + ((ktq * 4 + m) * 32 + lane) * 4;
                sm[base + (regc << 1)]     = pack_h2(acc[m][j][0] + bb.x,
                                                     acc[m][j][1] + bb.y);
                sm[base + 1 + (regc << 1)] = pack_h2(acc[m][j][2] + bb.x,
                                                     acc[m][j][3] + bb.y);
            }
        }
    }
    // pass 1: k
    {
        const int jt0 = 16 + warp * 2;       // 16..31
        float acc[4][2][4];
        gemm1_tiles(sm, lane, jt0, acc);
        #pragma unroll
        for (int j = 0; j < 2; j++) {
            int jg    = (jt0 + j) * 8;       // global col 128..255
            int j2    = jg - 128;
            int h     = j2 >> 5;
            int cl    = (j2 & 31) + tg * 2;
            float2 bb = *(const float2*)(g_qkvb + jg + tg * 2);
            int ktk   = cl >> 4;
            int reg   = (cl >> 3) & 1;
            #pragma unroll
            for (int m = 0; m < 4; m++) {
                sm[KF + h * 1024 + ((ktk * 8 + 2 * m) * 32 + lane) * 2 + reg] =
                    pack_h2(acc[m][j][0] + bb.x, acc[m][j][1] + bb.y);
                sm[KF + h * 1024 + ((ktk * 8 + 2 * m + 1) * 32 + lane) * 2 + reg] =
                    pack_h2(acc[m][j][2] + bb.x, acc[m][j][3] + bb.y);
            }
        }
    }
    // pass 2: v
    {
        const int jt0 = 32 + warp * 2;       // 32..47
        float acc[4][2][4];
        gemm1_tiles(sm, lane, jt0, acc);
        #pragma unroll
        for (int j = 0; j < 2; j++) {
            int jg    = (jt0 + j) * 8;       // global col 256..383
            int j2    = jg - 256;
            int h     = j2 >> 5;
            int cl    = (j2 & 31) + tg * 2;
            float2 bb = *(const float2*)(g_qkvb + jg + tg * 2);
            #pragma unroll
            for (int m = 0; m < 4; m++) {
                #pragma unroll
                for (int rs = 0; rs < 2; rs++) {
                    int t = m * 16 + g + 8 * rs;
                    #pragma unroll
                    for (int cs = 0; cs < 2; cs++) {
                        int   d   = cl + cs;
                        float val = acc[m][j][rs * 2 + cs] + (cs ? bb.y : bb.x);
                        int ktv = t >> 4;
                        int nt  = d >> 3;
                        int ln  = (d & 7) * 4 + ((t & 7) >> 1);
                        int reg = (t >> 3) & 1;
                        uint32_t slot = VF + h * 1024 + ((ktv * 4 + nt) * 32 + ln) * 2 + reg;
                        *reinterpret_cast<__half*>(smb + slot * 4 + (t & 1) * 2) =
                            __float2half_rn(val);
                    }
                }
            }
        }
    }
    __syncthreads();

    // prefetch next window's x tile into L2 (hides DRAM latency of next iter)
    {
        int bn = b + GRID_PERSIST;
        if (bn < B_TOT) {
            size_t off = (size_t)tid * 128;
            if (off < (size_t)NTOK * DIM * sizeof(float)) {
                const char* p = (const char*)(x + (size_t)bn * (NTOK * DIM)) + off;
                asm volatile("prefetch.global.L2 [%0];" :: "l"(p));
            }
        }
    }

    // ---------- fused S = q@k^T -> softmax -> PV, 2 units/warp ----------
    // unit u = (head h = u>>2, m-tile mt = u&3): 16 complete score rows.
    #pragma unroll 1
    for (int u = warp; u < 16; u += 8) {
        const int h  = u >> 2;
        const int mt = u & 3;

        // S: acc[jt][0..1] = rows r0, cols jt*8+2tg+{0,1}; [2..3] = row r0+8
        float acc[7][4];
        #pragma unroll
        for (int jt = 0; jt < 7; jt++)
            #pragma unroll
            for (int r = 0; r < 4; r++) acc[jt][r] = 0.f;

        #pragma unroll
        for (int kt = 0; kt < 2; ++kt) {
            uint4 af = *(const uint4*)(sm + QF + h * 1024 + ((kt * 4 + mt) * 32 + lane) * 4);
            #pragma unroll
            for (int jt = 0; jt < 7; ++jt) {
                uint2 bw = *(const uint2*)(sm + KF + h * 1024 + ((kt * 8 + jt) * 32 + lane) * 2);
                mma_f16(acc[jt], af.x, af.y, af.z, af.w, bw.x, bw.y);
            }
        }

        // bias + mask (pad cols arrive as -1e30 from the table)
        const int r0 = mt * 16 + g;
        const float* bm = g_bm + ((size_t)(b & (NW - 1)) * NH + h) * (BM_R * BM_C);
        #pragma unroll
        for (int jt = 0; jt < 7; ++jt) {
            int c0 = jt * 8 + tg * 2;
            float2 bv0 = __ldg((const float2*)(bm + r0 * BM_C + c0));
            float2 bv1 = __ldg((const float2*)(bm + (r0 + 8) * BM_C + c0));
            acc[jt][0] += bv0.x; acc[jt][1] += bv0.y;
            acc[jt][2] += bv1.x; acc[jt][3] += bv1.y;
        }

        // row-wise softmax: reduce 14 locals + 2 shuffles over the tg quartet
        float mx0 = -1e30f, mx1 = -1e30f;
        #pragma unroll
        for (int jt = 0; jt < 7; ++jt) {
            mx0 = fmaxf(mx0, fmaxf(acc[jt][0], acc[jt][1]));
            mx1 = fmaxf(mx1, fmaxf(acc[jt][2], acc[jt][3]));
        }
        #pragma unroll
        for (int o = 1; o <= 2; o <<= 1) {
            mx0 = fmaxf(mx0, __shfl_xor_sync(0xffffffffu, mx0, o));
            mx1 = fmaxf(mx1, __shfl_xor_sync(0xffffffffu, mx1, o));
        }
        float s0 = 0.f, s1 = 0.f;
        #pragma unroll
        for (int jt = 0; jt < 7; ++jt) {
            acc[jt][0] = __expf(acc[jt][0] - mx0); s0 += acc[jt][0];
            acc[jt][1] = __expf(acc[jt][1] - mx0); s0 += acc[jt][1];
            acc[jt][2] = __expf(acc[jt][2] - mx1); s1 += acc[jt][2];
            acc[jt][3] = __expf(acc[jt][3] - mx1); s1 += acc[jt][3];
        }
        #pragma unroll
        for (int o = 1; o <= 2; o <<= 1) {
            s0 += __shfl_xor_sync(0xffffffffu, s0, o);
            s1 += __shfl_xor_sync(0xffffffffu, s1, o);
        }
        float i0 = 1.f / s0, i1 = 1.f / s1;

        // P -> fp16 pairs; S C-layout == PV A-layout, so no smem round-trip
        uint32_t ph[7][2];
        #pragma unroll
        for (int jt = 0; jt < 7; ++jt) {
            ph[jt][0] = pack_h2(acc[jt][0] * i0, acc[jt][1] * i0);
            ph[jt][1] = pack_h2(acc[jt][2] * i1, acc[jt][3] * i1);
        }

        // PV: attnout[16 x 32] = P[16 x 64pad] @ V[64pad x 32]
        float po[4][4];
        #pragma unroll
        for (int n = 0; n < 4; n++)
            #pragma unroll
            for (int r = 0; r < 4; r++) po[n][r] = 0.f;

        #pragma unroll
        for (int kt = 0; kt < 4; ++kt) {
            uint32_t a0 = ph[2 * kt][0], a1 = ph[2 * kt][1];
            uint32_t a2 = (kt < 3) ? ph[2 * kt + 1][0] : 0u;
            uint32_t a3 = (kt < 3) ? ph[2 * kt + 1][1] : 0u;
            #pragma unroll
            for (int n = 0; n < 4; ++n) {
                uint2 bw = *(const uint2*)(sm + VF + h * 1024 + ((kt * 4 + n) * 32 + lane) * 2);
                mma_f16(po[n], a0, a1, a2, a3, bw.x, bw.y);
            }
        }

        // scatter into A-frag-linear attnout (reuses XF)
        #pragma unroll
        for (int n = 0; n < 4; ++n) {
            int cg   = h * 32 + n * 8 + tg * 2;
            int ktx  = cg >> 4;
            int regc = (cg >> 3) & 1;
            uint32_t base = XF + ((ktx * 4 + mt) * 32 + lane) * 4;
            sm[base + (regc << 1)]     = pack_h2(po[n][0], po[n][1]);
            sm[base + 1 + (regc << 1)] = pack_h2(po[n][2], po[n][3]);
        }
    }
    __syncthreads();

    // ---------- GEMM3: out = attnout @ proj_w^T + proj_b, 2 jtiles/warp ------
    {
        float acc[2][4][4];
        #pragma unroll
        for (int jj = 0; jj < 2; jj++)
            #pragma unroll
            for (int m = 0; m < 4; m++)
                #pragma unroll
                for (int r = 0; r < 4; r++) acc[jj][m][r] = 0.f;

        #pragma unroll
        for (int kt = 0; kt < 8; ++kt) {
            uint4 af[4];
            #pragma unroll
            for (int m = 0; m < 4; m++)
                af[m] = *(const uint4*)(sm + XF + ((kt * 4 + m) * 32 + lane) * 4);
            #pragma unroll
            for (int jj = 0; jj < 2; jj++) {
                int jt = warp + jj * 8;
                uint2 bw = __ldg(&g_wproj16[(kt * 16 + jt) * 32 + lane]);
                #pragma unroll
                for (int m = 0; m < 4; m++)
                    mma_f16(acc[jj][m], af[m].x, af[m].y, af[m].z, af[m].w, bw.x, bw.y);
            }
        }

        float* ob = out + (size_t)b * (NTOK * DIM);
        #pragma unroll
        for (int jj = 0; jj < 2; jj++) {
            int jt = warp + jj * 8;
            int c0 = jt * 8 + tg * 2;
            float pb0 = __ldg(proj_b + c0);
            float pb1 = __ldg(proj_b + c0 + 1);
            #pragma unroll
            for (int m = 0; m < 4; m++) {
                int row = m * 16 + g;
                if (row < NTOK) {
                    float2 v; v.x = acc[jj][m][0] + pb0; v.y = acc[jj][m][1] + pb1;
                    *(float2*)(ob + row * DIM + c0) = v;
                }
                if (row + 8 < NTOK) {
                    float2 v; v.x = acc[jj][m][2] + pb0; v.y = acc[jj][m][3] + pb1;
                    *(float2*)(ob + (row + 8) * DIM + c0) = v;
                }
            }
        }
    }

    }  // persistent window loop
}

// ---------------- launch ----------------
extern "C" void kernel_launch(void* const* d_in, const int* in_sizes, int n_in,
                              void* d_out, int out_size) {
    const float* x       = (const float*)d_in[0];
    const float* mask    = (const float*)d_in[1];
    const float* qkv_w   = (const float*)d_in[2];
    const float* qkv_b   = (const float*)d_in[3];
    const float* rpb     = (const float*)d_in[4];
    const float* proj_w  = (const float*)d_in[5];
    const float* proj_b  = (const float*)d_in[6];
    const int*   rel_idx = (const int*)d_in[7];
    float* out = (float*)d_out;

    const int total_bm = NW * NH * BM_R * BM_C;
    pack_all_kernel<<<(total_bm + 255) / 256, 256>>>(qkv_w, proj_w, qkv_b,
                                                     mask, rpb, rel_idx);

    cudaFuncSetAttribute(win_attn_kernel,
                         cudaFuncAttributeMaxDynamicSharedMemorySize,
                         SMEM_U32 * sizeof(uint32_t));
    win_attn_kernel<<<GRID_PERSIST, 256, SMEM_U32 * sizeof(uint32_t)>>>(x, proj_b, out);
}

// round 14
// speedup vs baseline: 1.1016x; 1.1016x over previous
#include <cuda_runtime.h>
#include <cuda_fp16.h>
#include <cstdint>
#include <cstddef>

#define B_TOT 4096
#define NTOK  49
#define DIM   128
#define NH    4
#define HD    32
#define NW    64
#define SCALE 0.17677669529663687f   // 32^-0.5

// ---------------- device scratch ----------------
// fp16 weight B-fragments packed in jtile PAIRS:
// per (kt, jtp, lane) -> uint4 {jt_even.b0, jt_even.b1, jt_odd.b0, jt_odd.b1}
// q rows (n < 128) pre-scaled by SCALE.
__device__ uint4 g_wqkv16p[8 * 24 * 32];
__device__ uint4 g_wproj16p[8 * 8 * 32];
__device__ float g_qkvb[384];          // qkv bias, q part pre-scaled
// bias+mask, padded: [NW][NH][64 rows][56 cols]; cols>=49 = -1e30, rows>=49 = 0
#define BM_R 64
#define BM_C 56
__device__ float g_bm[NW * NH * BM_R * BM_C];

// ---------------- helpers ----------------
__device__ __forceinline__ uint32_t pack_h2(float a, float b) {
    __half2 h = __floats2half2_rn(a, b);
    return *reinterpret_cast<uint32_t*>(&h);
}

__device__ __forceinline__ void mma_f16(float c[4],
                                        uint32_t a0, uint32_t a1, uint32_t a2, uint32_t a3,
                                        uint32_t b0, uint32_t b1) {
    asm volatile(
        "mma.sync.aligned.m16n8k16.row.col.f32.f16.f16.f32 "
        "{%0,%1,%2,%3}, {%4,%5,%6,%7}, {%8,%9}, {%0,%1,%2,%3};\n"
        : "+f"(c[0]), "+f"(c[1]), "+f"(c[2]), "+f"(c[3])
        : "r"(a0), "r"(a1), "r"(a2), "r"(a3), "r"(b0), "r"(b1));
}

// ---------------- merged prep kernel (one launch) ----------------
__global__ void pack_all_kernel(const float* __restrict__ qkv_w,
                                const float* __restrict__ proj_w,
                                const float* __restrict__ qkv_b,
                                const float* __restrict__ mask,
                                const float* __restrict__ rpb,
                                const int*   __restrict__ rel_index) {
    int idx = blockIdx.x * blockDim.x + threadIdx.x;

    if (idx < 8 * 24 * 32) {
        int kt   = idx / (24 * 32);
        int jtp  = (idx / 32) % 24;
        int lane = idx % 32;
        int ne   = (2 * jtp) * 8 + (lane >> 2);   // even jtile row
        int no   = ne + 8;                        // odd jtile row (same tensor)
        int k0   = kt * 16 + (lane & 3) * 2;
        float s  = (ne < 128) ? SCALE : 1.f;      // fold softmax scale into q
        uint4 v;
        v.x = pack_h2(qkv_w[ne * DIM + k0] * s,     qkv_w[ne * DIM + k0 + 1] * s);
        v.y = pack_h2(qkv_w[ne * DIM + k0 + 8] * s, qkv_w[ne * DIM + k0 + 9] * s);
        v.z = pack_h2(qkv_w[no * DIM + k0] * s,     qkv_w[no * DIM + k0 + 1] * s);
        v.w = pack_h2(qkv_w[no * DIM + k0 + 8] * s, qkv_w[no * DIM + k0 + 9] * s);
        g_wqkv16p[idx] = v;
    }
    if (idx < 8 * 8 * 32) {
        int kt   = idx / (8 * 32);
        int jtp  = (idx / 32) % 8;
        int lane = idx % 32;
        int ne   = (2 * jtp) * 8 + (lane >> 2);
        int no   = ne + 8;
        int k0   = kt * 16 + (lane & 3) * 2;
        uint4 v;
        v.x = pack_h2(proj_w[ne * DIM + k0],     proj_w[ne * DIM + k0 + 1]);
        v.y = pack_h2(proj_w[ne * DIM + k0 + 8], proj_w[ne * DIM + k0 + 9]);
        v.z = pack_h2(proj_w[no * DIM + k0],     proj_w[no * DIM + k0 + 1]);
        v.w = pack_h2(proj_w[no * DIM + k0 + 8], proj_w[no * DIM + k0 + 9]);
        g_wproj16p[idx] = v;
    }
    if (idx < 384) {
        g_qkvb[idx] = qkv_b[idx] * ((idx < 128) ? SCALE : 1.f);
    }

    const int total_bm = NW * NH * BM_R * BM_C;
    if (idx < total_bm) {
        int col = idx % BM_C;
        int row = (idx / BM_C) % BM_R;
        int h   = (idx / (BM_C * BM_R)) % NH;
        int w   = idx / (BM_C * BM_R * NH);
        float v;
        if (row < NTOK && col < NTOK) {
            int r = row * NTOK + col;
            v = rpb[rel_index[r] * NH + h] + mask[w * NTOK * NTOK + r];
        } else if (row < NTOK) {
            v = -1e30f;        // pad column: exp -> 0
        } else {
            v = 0.f;           // pad row: discarded later
        }
        g_bm[idx] = v;
    }
}

// ---------------- smem layout (uint32 units) ----------------
// XF @0      : 4096  x / attnout, A-frag-linear fp16  [64x128]
// QF @4096   : 4096  q per head, A-frag-linear fp16   [64x32] x4
// KF @8192   : 4096  k per head, B-frag-linear fp16   [n=64 tok][k=32 dim] x4
// VF @12288  : 4096  v per head, B-frag-linear fp16   [k=64 tok][n=32 dim] x4
#define XF 0
#define QF 4096
#define KF 8192
#define VF 12288
#define SMEM_U32 16384    // 65536 bytes; x3 CTAs = 192 KB/SM

extern __shared__ uint32_t smem_u32[];

// GEMM1 tile compute: 2 m-tiles (mhalf) x 4 jtiles (2 packed pairs from jtp0)
// acc[m][j][r]; A-loads = 16 LDS.128, B-loads = 16 LDG.128 per call
__device__ __forceinline__ void gemm1_tiles2(const uint32_t* sm, int lane,
                                             int mhalf, int jtp0,
                                             float acc[2][4][4]) {
    #pragma unroll
    for (int m = 0; m < 2; m++)
        #pragma unroll
        for (int j = 0; j < 4; j++)
            #pragma unroll
            for (int r = 0; r < 4; r++) acc[m][j][r] = 0.f;

    #pragma unroll
    for (int kt = 0; kt < 8; ++kt) {
        uint4 af[2];
        #pragma unroll
        for (int m = 0; m < 2; m++)
            af[m] = *(const uint4*)(sm + XF + ((kt * 4 + 2 * mhalf + m) * 32 + lane) * 4);
        #pragma unroll
        for (int jp = 0; jp < 2; ++jp) {
            uint4 bw = __ldg(&g_wqkv16p[(kt * 24 + jtp0 + jp) * 32 + lane]);
            #pragma unroll
            for (int m = 0; m < 2; m++) {
                mma_f16(acc[m][2 * jp],     af[m].x, af[m].y, af[m].z, af[m].w, bw.x, bw.y);
                mma_f16(acc[m][2 * jp + 1], af[m].x, af[m].y, af[m].z, af[m].w, bw.z, bw.w);
            }
        }
    }
}

__global__ void __launch_bounds__(256, 3)
win_attn_kernel(const float* __restrict__ x,
                const float* __restrict__ proj_b,
                float* __restrict__ out) {
    const int b    = blockIdx.x;
    const int tid  = threadIdx.x;
    const int warp = tid >> 5;       // 0..7
    const int lane = tid & 31;
    const int g    = lane >> 2;
    const int tg   = lane & 3;
    const int jq    = warp >> 1;     // 0..3: jtile quad
    const int mhalf = warp & 1;      // 0..1: which pair of m-tiles

    uint32_t* sm  = smem_u32;
    char*     smb = reinterpret_cast<char*>(smem_u32);

    // load x into A-frag-linear fp16; pad rows (>=49) written as zero directly
    const float* xb = x + (size_t)b * (NTOK * DIM);
    #pragma unroll
    for (int i = tid; i < 64 * 64; i += 256) {
        int r  = i >> 6;
        int c2 = i & 63;
        int c  = c2 * 2;
        uint32_t val = 0u;
        if (r < NTOK) {
            float2 v = *(const float2*)(xb + r * DIM + c);
            val = pack_h2(v.x, v.y);
        }
        int kt   = c >> 4;
        int m    = r >> 4;
        int ln   = (r & 7) * 4 + (c2 & 3);
        int reg  = ((r >> 3) & 1) | (((c >> 3) & 1) << 1);
        sm[XF + ((kt * 4 + m) * 32 + ln) * 4 + reg] = val;
    }
    __syncthreads();

    // ---------- GEMM1: 3 passes x (2m x 4j)/warp; pass 0=q, 1=k, 2=v ---------
    // pass 0: q (weights+bias pre-scaled by SCALE)
    {
        float acc[2][4][4];
        gemm1_tiles2(sm, lane, mhalf, jq * 2, acc);
        #pragma unroll
        for (int j = 0; j < 4; j++) {
            int jbase = (jq * 4 + j) * 8;    // 0..127
            int h     = jbase >> 5;
            int cl    = (jbase & 31) + tg * 2;
            float2 bb = *(const float2*)(g_qkvb + jbase + tg * 2);
            int ktq   = cl >> 4;
            int regc  = (cl >> 3) & 1;
            #pragma unroll
            for (int m = 0; m < 2; m++) {
                int mt = 2 * mhalf + m;
                uint32_t base = QF + h * 1024 + ((ktq * 4 + mt) * 32 + lane) * 4;
                sm[base + (regc << 1)]     = pack_h2(acc[m][j][0] + bb.x,
                                                     acc[m][j][1] + bb.y);
                sm[base + 1 + (regc << 1)] = pack_h2(acc[m][j][2] + bb.x,
                                                     acc[m][j][3] + bb.y);
            }
        }
    }
    // pass 1: k
    {
        float acc[2][4][4];
        gemm1_tiles2(sm, lane, mhalf, 8 + jq * 2, acc);
        #pragma unroll
        for (int j = 0; j < 4; j++) {
            int j2    = (jq * 4 + j) * 8;    // head-space col 0..127
            int jg    = 128 + j2;            // global col
            int h     = j2 >> 5;
            int cl    = (j2 & 31) + tg * 2;
            float2 bb = *(const float2*)(g_qkvb + jg + tg * 2);
            int ktk   = cl >> 4;
            int reg   = (cl >> 3) & 1;
            #pragma unroll
            for (int m = 0; m < 2; m++) {
                int mt = 2 * mhalf + m;
                sm[KF + h * 1024 + ((ktk * 8 + 2 * mt) * 32 + lane) * 2 + reg] =
                    pack_h2(acc[m][j][0] + bb.x, acc[m][j][1] + bb.y);
                sm[KF + h * 1024 + ((ktk * 8 + 2 * mt + 1) * 32 + lane) * 2 + reg] =
                    pack_h2(acc[m][j][2] + bb.x, acc[m][j][3] + bb.y);
            }
        }
    }
    // pass 2: v
    {
        float acc[2][4][4];
        gemm1_tiles2(sm, lane, mhalf, 16 + jq * 2, acc);
        #pragma unroll
        for (int j = 0; j < 4; j++) {
            int j2    = (jq * 4 + j) * 8;    // head-space col 0..127
            int jg    = 256 + j2;
            int h     = j2 >> 5;
            int cl    = (j2 & 31) + tg * 2;
            float2 bb = *(const float2*)(g_qkvb + jg + tg * 2);
            #pragma unroll
            for (int m = 0; m < 2; m++) {
                int mt = 2 * mhalf + m;
                #pragma unroll
                for (int rs = 0; rs < 2; rs++) {
                    int t = mt * 16 + g + 8 * rs;
                    #pragma unroll
                    for (int cs = 0; cs < 2; cs++) {
                        int   d   = cl + cs;
                        float val = acc[m][j][rs * 2 + cs] + (cs ? bb.y : bb.x);
                        int ktv = t >> 4;
                        int nt  = d >> 3;
                        int ln  = (d & 7) * 4 + ((t & 7) >> 1);
                        int reg = (t >> 3) & 1;
                        uint32_t slot = VF + h * 1024 + ((ktv * 4 + nt) * 32 + ln) * 2 + reg;
                        *reinterpret_cast<__half*>(smb + slot * 4 + (t & 1) * 2) =
                            __float2half_rn(val);
                    }
                }
            }
        }
    }
    __syncthreads();

    // ---------- fused S = q@k^T -> softmax -> PV, 2 units/warp ----------
    // unit u = (head h = u>>2, m-tile mt = u&3): 16 complete score rows.
    #pragma unroll 1
    for (int u = warp; u < 16; u += 8) {
        const int h  = u >> 2;
        const int mt = u & 3;

        // S: acc[jt][0..1] = rows r0, cols jt*8+2tg+{0,1}; [2..3] = row r0+8
        float acc[7][4];
        #pragma unroll
        for (int jt = 0; jt < 7; jt++)
            #pragma unroll
            for (int r = 0; r < 4; r++) acc[jt][r] = 0.f;

        #pragma unroll
        for (int kt = 0; kt < 2; ++kt) {
            uint4 af = *(const uint4*)(sm + QF + h * 1024 + ((kt * 4 + mt) * 32 + lane) * 4);
            #pragma unroll
            for (int jt = 0; jt < 7; ++jt) {
                uint2 bw = *(const uint2*)(sm + KF + h * 1024 + ((kt * 8 + jt) * 32 + lane) * 2);
                mma_f16(acc[jt], af.x, af.y, af.z, af.w, bw.x, bw.y);
            }
        }

        // bias + mask (pad cols arrive as -1e30 from the table)
        const int r0 = mt * 16 + g;
        const float* bm = g_bm + ((size_t)(b & (NW - 1)) * NH + h) * (BM_R * BM_C);
        #pragma unroll
        for (int jt = 0; jt < 7; ++jt) {
            int c0 = jt * 8 + tg * 2;
            float2 bv0 = __ldg((const float2*)(bm + r0 * BM_C + c0));
            float2 bv1 = __ldg((const float2*)(bm + (r0 + 8) * BM_C + c0));
            acc[jt][0] += bv0.x; acc[jt][1] += bv0.y;
            acc[jt][2] += bv1.x; acc[jt][3] += bv1.y;
        }

        // row-wise softmax: reduce 14 locals + 2 shuffles over the tg quartet
        float mx0 = -1e30f, mx1 = -1e30f;
        #pragma unroll
        for (int jt = 0; jt < 7; ++jt) {
            mx0 = fmaxf(mx0, fmaxf(acc[jt][0], acc[jt][1]));
            mx1 = fmaxf(mx1, fmaxf(acc[jt][2], acc[jt][3]));
        }
        #pragma unroll
        for (int o = 1; o <= 2; o <<= 1) {
            mx0 = fmaxf(mx0, __shfl_xor_sync(0xffffffffu, mx0, o));
            mx1 = fmaxf(mx1, __shfl_xor_sync(0xffffffffu, mx1, o));
        }
        float s0 = 0.f, s1 = 0.f;
        #pragma unroll
        for (int jt = 0; jt < 7; ++jt) {
            acc[jt][0] = __expf(acc[jt][0] - mx0); s0 += acc[jt][0];
            acc[jt][1] = __expf(acc[jt][1] - mx0); s0 += acc[jt][1];
            acc[jt][2] = __expf(acc[jt][2] - mx1); s1 += acc[jt][2];
            acc[jt][3] = __expf(acc[jt][3] - mx1); s1 += acc[jt][3];
        }
        #pragma unroll
        for (int o = 1; o <= 2; o <<= 1) {
            s0 += __shfl_xor_sync(0xffffffffu, s0, o);
            s1 += __shfl_xor_sync(0xffffffffu, s1, o);
        }
        float i0 = 1.f / s0, i1 = 1.f / s1;

        // P -> fp16 pairs; S C-layout == PV A-layout, so no smem round-trip
        uint32_t ph[7][2];
        #pragma unroll
        for (int jt = 0; jt < 7; ++jt) {
            ph[jt][0] = pack_h2(acc[jt][0] * i0, acc[jt][1] * i0);
            ph[jt][1] = pack_h2(acc[jt][2] * i1, acc[jt][3] * i1);
        }

        // PV: attnout[16 x 32] = P[16 x 64pad] @ V[64pad x 32]
        float po[4][4];
        #pragma unroll
        for (int n = 0; n < 4; n++)
            #pragma unroll
            for (int r = 0; r < 4; r++) po[n][r] = 0.f;

        #pragma unroll
        for (int kt = 0; kt < 4; ++kt) {
            uint32_t a0 = ph[2 * kt][0], a1 = ph[2 * kt][1];
            uint32_t a2 = (kt < 3) ? ph[2 * kt + 1][0] : 0u;
            uint32_t a3 = (kt < 3) ? ph[2 * kt + 1][1] : 0u;
            #pragma unroll
            for (int n = 0; n < 4; ++n) {
                uint2 bw = *(const uint2*)(sm + VF + h * 1024 + ((kt * 4 + n) * 32 + lane) * 2);
                mma_f16(po[n], a0, a1, a2, a3, bw.x, bw.y);
            }
        }

        // scatter into A-frag-linear attnout (reuses XF)
        #pragma unroll
        for (int n = 0; n < 4; ++n) {
            int cg   = h * 32 + n * 8 + tg * 2;
            int ktx  = cg >> 4;
            int regc = (cg >> 3) & 1;
            uint32_t base = XF + ((ktx * 4 + mt) * 32 + lane) * 4;
            sm[base + (regc << 1)]     = pack_h2(po[n][0], po[n][1]);
            sm[base + 1 + (regc << 1)] = pack_h2(po[n][2], po[n][3]);
        }
    }
    __syncthreads();

    // ---------- GEMM3: out = attnout @ proj_w^T + proj_b, jt pair/warp -------
    {
        float acc[2][4][4];
        #pragma unroll
        for (int jj = 0; jj < 2; jj++)
            #pragma unroll
            for (int m = 0; m < 4; m++)
                #pragma unroll
                for (int r = 0; r < 4; r++) acc[jj][m][r] = 0.f;

        #pragma unroll
        for (int kt = 0; kt < 8; ++kt) {
            uint4 af[4];
            #pragma unroll
            for (int m = 0; m < 4; m++)
                af[m] = *(const uint4*)(sm + XF + ((kt * 4 + m) * 32 + lane) * 4);
            uint4 bw = __ldg(&g_wproj16p[(kt * 8 + warp) * 32 + lane]);
            #pragma unroll
            for (int m = 0; m < 4; m++) {
                mma_f16(acc[0][m], af[m].x, af[m].y, af[m].z, af[m].w, bw.x, bw.y);
                mma_f16(acc[1][m], af[m].x, af[m].y, af[m].z, af[m].w, bw.z, bw.w);
            }
        }

        float* ob = out + (size_t)b * (NTOK * DIM);
        #pragma unroll
        for (int jj = 0; jj < 2; jj++) {
            int jt = 2 * warp + jj;
            int c0 = jt * 8 + tg * 2;
            float pb0 = __ldg(proj_b + c0);
            float pb1 = __ldg(proj_b + c0 + 1);
            #pragma unroll
            for (int m = 0; m < 4; m++) {
                int row = m * 16 + g;
                if (row < NTOK) {
                    float2 v; v.x = acc[jj][m][0] + pb0; v.y = acc[jj][m][1] + pb1;
                    *(float2*)(ob + row * DIM + c0) = v;
                }
                if (row + 8 < NTOK) {
                    float2 v; v.x = acc[jj][m][2] + pb0; v.y = acc[jj][m][3] + pb1;
                    *(float2*)(ob + (row + 8) * DIM + c0) = v;
                }
            }
        }
    }
}

// ---------------- launch ----------------
extern "C" void kernel_launch(void* const* d_in, const int* in_sizes, int n_in,
                              void* d_out, int out_size) {
    const float* x       = (const float*)d_in[0];
    const float* mask    = (const float*)d_in[1];
    const float* qkv_w   = (const float*)d_in[2];
    const float* qkv_b   = (const float*)d_in[3];
    const float* rpb     = (const float*)d_in[4];
    const float* proj_w  = (const float*)d_in[5];
    const float* proj_b  = (const float*)d_in[6];
    const int*   rel_idx = (const int*)d_in[7];
    float* out = (float*)d_out;

    const int total_bm = NW * NH * BM_R * BM_C;
    pack_all_kernel<<<(total_bm + 255) / 256, 256>>>(qkv_w, proj_w, qkv_b,
                                                     mask, rpb, rel_idx);

    cudaFuncSetAttribute(win_attn_kernel,
                         cudaFuncAttributeMaxDynamicSharedMemorySize,
                         SMEM_U32 * sizeof(uint32_t));
    win_attn_kernel<<<B_TOT, 256, SMEM_U32 * sizeof(uint32_t)>>>(x, proj_b, out);
}

// round 16
// speedup vs baseline: 1.1578x; 1.0510x over previous
#include <cuda_runtime.h>
#include <cuda_fp16.h>
#include <cstdint>
#include <cstddef>

#define B_TOT 4096
#define NTOK  49
#define DIM   128
#define NH    4
#define HD    32
#define NW    64
#define SCALE 0.17677669529663687f   // 32^-0.5

// ---------------- device scratch ----------------
// fp16 weight B-fragments packed in jtile PAIRS:
// per (kt, jtp, lane) -> uint4 {jt_even.b0, jt_even.b1, jt_odd.b0, jt_odd.b1}
// q rows (n < 128) pre-scaled by SCALE.
__device__ uint4 g_wqkv16p[8 * 24 * 32];
__device__ uint4 g_wproj16p[8 * 8 * 32];
__device__ float g_qkvb[384];          // qkv bias, q part pre-scaled
// bias+mask, padded: [NW][NH][64 rows][56 cols]; cols>=49 = -1e30, rows>=49 = 0
#define BM_R 64
#define BM_C 56
__device__ float g_bm[NW * NH * BM_R * BM_C];

// ---------------- helpers ----------------
__device__ __forceinline__ uint32_t pack_h2(float a, float b) {
    __half2 h = __floats2half2_rn(a, b);
    return *reinterpret_cast<uint32_t*>(&h);
}

__device__ __forceinline__ void mma_f16(float c[4],
                                        uint32_t a0, uint32_t a1, uint32_t a2, uint32_t a3,
                                        uint32_t b0, uint32_t b1) {
    asm volatile(
        "mma.sync.aligned.m16n8k16.row.col.f32.f16.f16.f32 "
        "{%0,%1,%2,%3}, {%4,%5,%6,%7}, {%8,%9}, {%0,%1,%2,%3};\n"
        : "+f"(c[0]), "+f"(c[1]), "+f"(c[2]), "+f"(c[3])
        : "r"(a0), "r"(a1), "r"(a2), "r"(a3), "r"(b0), "r"(b1));
}

// ---------------- merged prep kernel (one launch) ----------------
__global__ void pack_all_kernel(const float* __restrict__ qkv_w,
                                const float* __restrict__ proj_w,
                                const float* __restrict__ qkv_b,
                                const float* __restrict__ mask,
                                const float* __restrict__ rpb,
                                const int*   __restrict__ rel_index) {
    int idx = blockIdx.x * blockDim.x + threadIdx.x;

    if (idx < 8 * 24 * 32) {
        int kt   = idx / (24 * 32);
        int jtp  = (idx / 32) % 24;
        int lane = idx % 32;
        int ne   = (2 * jtp) * 8 + (lane >> 2);   // even jtile row
        int no   = ne + 8;                        // odd jtile row (same tensor)
        int k0   = kt * 16 + (lane & 3) * 2;
        float s  = (ne < 128) ? SCALE : 1.f;      // fold softmax scale into q
        uint4 v;
        v.x = pack_h2(qkv_w[ne * DIM + k0] * s,     qkv_w[ne * DIM + k0 + 1] * s);
        v.y = pack_h2(qkv_w[ne * DIM + k0 + 8] * s, qkv_w[ne * DIM + k0 + 9] * s);
        v.z = pack_h2(qkv_w[no * DIM + k0] * s,     qkv_w[no * DIM + k0 + 1] * s);
        v.w = pack_h2(qkv_w[no * DIM + k0 + 8] * s, qkv_w[no * DIM + k0 + 9] * s);
        g_wqkv16p[idx] = v;
    }
    if (idx < 8 * 8 * 32) {
        int kt   = idx / (8 * 32);
        int jtp  = (idx / 32) % 8;
        int lane = idx % 32;
        int ne   = (2 * jtp) * 8 + (lane >> 2);
        int no   = ne + 8;
        int k0   = kt * 16 + (lane & 3) * 2;
        uint4 v;
        v.x = pack_h2(proj_w[ne * DIM + k0],     proj_w[ne * DIM + k0 + 1]);
        v.y = pack_h2(proj_w[ne * DIM + k0 + 8], proj_w[ne * DIM + k0 + 9]);
        v.z = pack_h2(proj_w[no * DIM + k0],     proj_w[no * DIM + k0 + 1]);
        v.w = pack_h2(proj_w[no * DIM + k0 + 8], proj_w[no * DIM + k0 + 9]);
        g_wproj16p[idx] = v;
    }
    if (idx < 384) {
        g_qkvb[idx] = qkv_b[idx] * ((idx < 128) ? SCALE : 1.f);
    }

    const int total_bm = NW * NH * BM_R * BM_C;
    if (idx < total_bm) {
        int col = idx % BM_C;
        int row = (idx / BM_C) % BM_R;
        int h   = (idx / (BM_C * BM_R)) % NH;
        int w   = idx / (BM_C * BM_R * NH);
        float v;
        if (row < NTOK && col < NTOK) {
            int r = row * NTOK + col;
            v = rpb[rel_index[r] * NH + h] + mask[w * NTOK * NTOK + r];
        } else if (row < NTOK) {
            v = -1e30f;        // pad column: exp -> 0
        } else {
            v = 0.f;           // pad row: discarded later
        }
        g_bm[idx] = v;
    }
}

// ---------------- smem layout (uint32 units) ----------------
// XF @0      : 4096  x / attnout, A-frag-linear fp16  [64x128]
// KF @4096   : 4096  k per head, B-frag-linear fp16   [n=64 tok][k=32 dim] x4
// VF @8192   : 4096  v per head, B-frag-linear fp16   [k=64 tok][n=32 dim] x4
#define XF 0
#define KF 4096
#define VF 8192
#define SMEM_U32 12288    // 49152 bytes; x3 CTAs = 144 KB/SM (L1D carveout 84 KB)

extern __shared__ uint32_t smem_u32[];

// GEMM1 tile compute: 2 m-tiles (mhalf) x 4 jtiles (2 packed pairs from jtp0)
// acc[m][j][r]; A-loads = 16 LDS.128, B-loads = 16 LDG.128 per call
__device__ __forceinline__ void gemm1_tiles2(const uint32_t* sm, int lane,
                                             int mhalf, int jtp0,
                                             float acc[2][4][4]) {
    #pragma unroll
    for (int m = 0; m < 2; m++)
        #pragma unroll
        for (int j = 0; j < 4; j++)
            #pragma unroll
            for (int r = 0; r < 4; r++) acc[m][j][r] = 0.f;

    #pragma unroll
    for (int kt = 0; kt < 8; ++kt) {
        uint4 af[2];
        #pragma unroll
        for (int m = 0; m < 2; m++)
            af[m] = *(const uint4*)(sm + XF + ((kt * 4 + 2 * mhalf + m) * 32 + lane) * 4);
        #pragma unroll
        for (int jp = 0; jp < 2; ++jp) {
            uint4 bw = __ldg(&g_wqkv16p[(kt * 24 + jtp0 + jp) * 32 + lane]);
            #pragma unroll
            for (int m = 0; m < 2; m++) {
                mma_f16(acc[m][2 * jp],     af[m].x, af[m].y, af[m].z, af[m].w, bw.x, bw.y);
                mma_f16(acc[m][2 * jp + 1], af[m].x, af[m].y, af[m].z, af[m].w, bw.z, bw.w);
            }
        }
    }
}

__global__ void __launch_bounds__(256, 3)
win_attn_kernel(const float* __restrict__ x,
                const float* __restrict__ proj_b,
                float* __restrict__ out) {
    const int b    = blockIdx.x;
    const int tid  = threadIdx.x;
    const int warp = tid >> 5;       // 0..7
    const int lane = tid & 31;
    const int g    = lane >> 2;
    const int tg   = lane & 3;
    const int jq    = warp >> 1;     // 0..3: jtile quad / head id
    const int mhalf = warp & 1;      // 0..1: which pair of m-tiles

    uint32_t* sm  = smem_u32;
    char*     smb = reinterpret_cast<char*>(smem_u32);

    // load x into A-frag-linear fp16; pad rows (>=49) written as zero directly
    const float* xb = x + (size_t)b * (NTOK * DIM);
    #pragma unroll
    for (int i = tid; i < 64 * 64; i += 256) {
        int r  = i >> 6;
        int c2 = i & 63;
        int c  = c2 * 2;
        uint32_t val = 0u;
        if (r < NTOK) {
            float2 v = *(const float2*)(xb + r * DIM + c);
            val = pack_h2(v.x, v.y);
        }
        int kt   = c >> 4;
        int m    = r >> 4;
        int ln   = (r & 7) * 4 + (c2 & 3);
        int reg  = ((r >> 3) & 1) | (((c >> 3) & 1) << 1);
        sm[XF + ((kt * 4 + m) * 32 + ln) * 4 + reg] = val;
    }
    __syncthreads();

    // q A-fragments kept in registers: qh[m][chunk][a0..a3]
    uint32_t qh[2][2][4];

    // ---------- GEMM1: 3 passes x (2m x 4j)/warp; order k, v, then q ---------
    // pass k
    {
        float acc[2][4][4];
        gemm1_tiles2(sm, lane, mhalf, 8 + jq * 2, acc);
        #pragma unroll
        for (int j = 0; j < 4; j++) {
            int j2    = (jq * 4 + j) * 8;    // head-space col 0..127
            int jg    = 128 + j2;            // global col
            int h     = j2 >> 5;
            int cl    = (j2 & 31) + tg * 2;
            float2 bb = *(const float2*)(g_qkvb + jg + tg * 2);
            int ktk   = cl >> 4;
            int reg   = (cl >> 3) & 1;
            #pragma unroll
            for (int m = 0; m < 2; m++) {
                int mt = 2 * mhalf + m;
                sm[KF + h * 1024 + ((ktk * 8 + 2 * mt) * 32 + lane) * 2 + reg] =
                    pack_h2(acc[m][j][0] + bb.x, acc[m][j][1] + bb.y);
                sm[KF + h * 1024 + ((ktk * 8 + 2 * mt + 1) * 32 + lane) * 2 + reg] =
                    pack_h2(acc[m][j][2] + bb.x, acc[m][j][3] + bb.y);
            }
        }
    }
    // pass v
    {
        float acc[2][4][4];
        gemm1_tiles2(sm, lane, mhalf, 16 + jq * 2, acc);
        #pragma unroll
        for (int j = 0; j < 4; j++) {
            int j2    = (jq * 4 + j) * 8;    // head-space col 0..127
            int jg    = 256 + j2;
            int h     = j2 >> 5;
            int cl    = (j2 & 31) + tg * 2;
            float2 bb = *(const float2*)(g_qkvb + jg + tg * 2);
            #pragma unroll
            for (int m = 0; m < 2; m++) {
                int mt = 2 * mhalf + m;
                #pragma unroll
                for (int rs = 0; rs < 2; rs++) {
                    int t = mt * 16 + g + 8 * rs;
                    #pragma unroll
                    for (int cs = 0; cs < 2; cs++) {
                        int   d   = cl + cs;
                        float val = acc[m][j][rs * 2 + cs] + (cs ? bb.y : bb.x);
                        int ktv = t >> 4;
                        int nt  = d >> 3;
                        int ln  = (d & 7) * 4 + ((t & 7) >> 1);
                        int reg = (t >> 3) & 1;
                        uint32_t slot = VF + h * 1024 + ((ktv * 4 + nt) * 32 + ln) * 2 + reg;
                        *reinterpret_cast<__half*>(smb + slot * 4 + (t & 1) * 2) =
                            __float2half_rn(val);
                    }
                }
            }
        }
    }
    // pass q -> registers only (this warp is also the consumer: h = jq)
    {
        float acc[2][4][4];
        gemm1_tiles2(sm, lane, mhalf, jq * 2, acc);
        #pragma unroll
        for (int j = 0; j < 4; j++) {
            int jbase = (jq * 4 + j) * 8;    // 0..127 == h*32 + local dim
            float2 bb = *(const float2*)(g_qkvb + jbase + tg * 2);
            int c = j >> 1;      // 16-dim chunk
            int o = j & 1;       // low/high 8 cols within chunk
            #pragma unroll
            for (int m = 0; m < 2; m++) {
                qh[m][c][2 * o]     = pack_h2(acc[m][j][0] + bb.x, acc[m][j][1] + bb.y);
                qh[m][c][2 * o + 1] = pack_h2(acc[m][j][2] + bb.x, acc[m][j][3] + bb.y);
            }
        }
    }
    __syncthreads();

    // ---------- fused S = q@k^T -> softmax -> PV; h = jq, mt = 2*mhalf+m -----
    const int h = jq;
    #pragma unroll
    for (int m = 0; m < 2; ++m) {
        const int mt = 2 * mhalf + m;

        // S: acc[jt][0..1] = rows r0, cols jt*8+2tg+{0,1}; [2..3] = row r0+8
        float acc[7][4];
        #pragma unroll
        for (int jt = 0; jt < 7; jt++)
            #pragma unroll
            for (int r = 0; r < 4; r++) acc[jt][r] = 0.f;

        #pragma unroll
        for (int c = 0; c < 2; ++c) {
            uint32_t a0 = qh[m][c][0], a1 = qh[m][c][1];
            uint32_t a2 = qh[m][c][2], a3 = qh[m][c][3];
            #pragma unroll
            for (int jt = 0; jt < 7; ++jt) {
                uint2 bw = *(const uint2*)(sm + KF + h * 1024 + ((c * 8 + jt) * 32 + lane) * 2);
                mma_f16(acc[jt], a0, a1, a2, a3, bw.x, bw.y);
            }
        }

        // bias + mask (pad cols arrive as -1e30 from the table)
        const int r0 = mt * 16 + g;
        const float* bm = g_bm + ((size_t)(b & (NW - 1)) * NH + h) * (BM_R * BM_C);
        #pragma unroll
        for (int jt = 0; jt < 7; ++jt) {
            int c0 = jt * 8 + tg * 2;
            float2 bv0 = __ldg((const float2*)(bm + r0 * BM_C + c0));
            float2 bv1 = __ldg((const float2*)(bm + (r0 + 8) * BM_C + c0));
            acc[jt][0] += bv0.x; acc[jt][1] += bv0.y;
            acc[jt][2] += bv1.x; acc[jt][3] += bv1.y;
        }

        // row-wise softmax: reduce 14 locals + 2 shuffles over the tg quartet
        float mx0 = -1e30f, mx1 = -1e30f;
        #pragma unroll
        for (int jt = 0; jt < 7; ++jt) {
            mx0 = fmaxf(mx0, fmaxf(acc[jt][0], acc[jt][1]));
            mx1 = fmaxf(mx1, fmaxf(acc[jt][2], acc[jt][3]));
        }
        #pragma unroll
        for (int o = 1; o <= 2; o <<= 1) {
            mx0 = fmaxf(mx0, __shfl_xor_sync(0xffffffffu, mx0, o));
            mx1 = fmaxf(mx1, __shfl_xor_sync(0xffffffffu, mx1, o));
        }
        float s0 = 0.f, s1 = 0.f;
        #pragma unroll
        for (int jt = 0; jt < 7; ++jt) {
            acc[jt][0] = __expf(acc[jt][0] - mx0); s0 += acc[jt][0];
            acc[jt][1] = __expf(acc[jt][1] - mx0); s0 += acc[jt][1];
            acc[jt][2] = __expf(acc[jt][2] - mx1); s1 += acc[jt][2];
            acc[jt][3] = __expf(acc[jt][3] - mx1); s1 += acc[jt][3];
        }
        #pragma unroll
        for (int o = 1; o <= 2; o <<= 1) {
            s0 += __shfl_xor_sync(0xffffffffu, s0, o);
            s1 += __shfl_xor_sync(0xffffffffu, s1, o);
        }
        float i0 = 1.f / s0, i1 = 1.f / s1;

        // P -> fp16 pairs; S C-layout == PV A-layout, so no smem round-trip
        uint32_t ph[7][2];
        #pragma unroll
        for (int jt = 0; jt < 7; ++jt) {
            ph[jt][0] = pack_h2(acc[jt][0] * i0, acc[jt][1] * i0);
            ph[jt][1] = pack_h2(acc[jt][2] * i1, acc[jt][3] * i1);
        }

        // PV: attnout[16 x 32] = P[16 x 64pad] @ V[64pad x 32]
        float po[4][4];
        #pragma unroll
        for (int n = 0; n < 4; n++)
            #pragma unroll
            for (int r = 0; r < 4; r++) po[n][r] = 0.f;

        #pragma unroll
        for (int kt = 0; kt < 4; ++kt) {
            uint32_t a0 = ph[2 * kt][0], a1 = ph[2 * kt][1];
            uint32_t a2 = (kt < 3) ? ph[2 * kt + 1][0] : 0u;
            uint32_t a3 = (kt < 3) ? ph[2 * kt + 1][1] : 0u;
            #pragma unroll
            for (int n = 0; n < 4; ++n) {
                uint2 bw = *(const uint2*)(sm + VF + h * 1024 + ((kt * 4 + n) * 32 + lane) * 2);
                mma_f16(po[n], a0, a1, a2, a3, bw.x, bw.y);
            }
        }

        // scatter into A-frag-linear attnout (reuses XF)
        #pragma unroll
        for (int n = 0; n < 4; ++n) {
            int cg   = h * 32 + n * 8 + tg * 2;
            int ktx  = cg >> 4;
            int regc = (cg >> 3) & 1;
            uint32_t base = XF + ((ktx * 4 + mt) * 32 + lane) * 4;
            sm[base + (regc << 1)]     = pack_h2(po[n][0], po[n][1]);
            sm[base + 1 + (regc << 1)] = pack_h2(po[n][2], po[n][3]);
        }
    }
    __syncthreads();

    // ---------- GEMM3: out = attnout @ proj_w^T + proj_b, (2m x 4j)/warp -----
    {
        float acc[2][4][4];
        #pragma unroll
        for (int m = 0; m < 2; m++)
            #pragma unroll
            for (int j = 0; j < 4; j++)
                #pragma unroll
                for (int r = 0; r < 4; r++) acc[m][j][r] = 0.f;

        #pragma unroll
        for (int kt = 0; kt < 8; ++kt) {
            uint4 af[2];
            #pragma unroll
            for (int m = 0; m < 2; m++)
                af[m] = *(const uint4*)(sm + XF + ((kt * 4 + 2 * mhalf + m) * 32 + lane) * 4);
            #pragma unroll
            for (int jp = 0; jp < 2; ++jp) {
                uint4 bw = __ldg(&g_wproj16p[(kt * 8 + jq * 2 + jp) * 32 + lane]);
                #pragma unroll
                for (int m = 0; m < 2; m++) {
                    mma_f16(acc[m][2 * jp],     af[m].x, af[m].y, af[m].z, af[m].w, bw.x, bw.y);
                    mma_f16(acc[m][2 * jp + 1], af[m].x, af[m].y, af[m].z, af[m].w, bw.z, bw.w);
                }
            }
        }

        float* ob = out + (size_t)b * (NTOK * DIM);
        #pragma unroll
        for (int j = 0; j < 4; j++) {
            int jt = jq * 4 + j;
            int c0 = jt * 8 + tg * 2;
            float pb0 = __ldg(proj_b + c0);
            float pb1 = __ldg(proj_b + c0 + 1);
            #pragma unroll
            for (int m = 0; m < 2; m++) {
                int row = (2 * mhalf + m) * 16 + g;
                if (row < NTOK) {
                    float2 v; v.x = acc[m][j][0] + pb0; v.y = acc[m][j][1] + pb1;
                    *(float2*)(ob + row * DIM + c0) = v;
                }
                if (row + 8 < NTOK) {
                    float2 v; v.x = acc[m][j][2] + pb0; v.y = acc[m][j][3] + pb1;
                    *(float2*)(ob + (row + 8) * DIM + c0) = v;
                }
            }
        }
    }
}

// ---------------- launch ----------------
extern "C" void kernel_launch(void* const* d_in, const int* in_sizes, int n_in,
                              void* d_out, int out_size) {
    const float* x       = (const float*)d_in[0];
    const float* mask    = (const float*)d_in[1];
    const float* qkv_w   = (const float*)d_in[2];
    const float* qkv_b   = (const float*)d_in[3];
    const float* rpb     = (const float*)d_in[4];
    const float* proj_w  = (const float*)d_in[5];
    const float* proj_b  = (const float*)d_in[6];
    const int*   rel_idx = (const int*)d_in[7];
    float* out = (float*)d_out;

    const int total_bm = NW * NH * BM_R * BM_C;
    pack_all_kernel<<<(total_bm + 255) / 256, 256>>>(qkv_w, proj_w, qkv_b,
                                                     mask, rpb, rel_idx);

    cudaFuncSetAttribute(win_attn_kernel,
                         cudaFuncAttributeMaxDynamicSharedMemorySize,
                         SMEM_U32 * sizeof(uint32_t));
    win_attn_kernel<<<B_TOT, 256, SMEM_U32 * sizeof(uint32_t)>>>(x, proj_b, out);
}